// round 17
// baseline (speedup 1.0000x reference)
#include <cuda_runtime.h>
#include <cuda_fp16.h>
#include <math.h>
#include <stdint.h>

// ===========================================================================
// ImplicitMap_fExtrator — Round 16: finer CTA granularity.
// Same algorithm as r15 (3-term fp16-split x-pass storing fp32 gates;
// 2-term single-fp16 reverse sweep). CTA tile shrunk 128x128 -> 64x128
// (4 warps, 128 thr, warp tile 64x32 unchanged) so grids double and
// 3 CTAs/SM fit -> CTA-slot quantization idle drops ~28% -> ~4% on the
// ragged layer grids.
// ===========================================================================

#define NPTS   16384
#define PITCH  960

__device__ __half g_xhiA[(size_t)NPTS * PITCH];
__device__ __half g_xloA[(size_t)NPTS * PITCH];
__device__ __half g_xhiB[(size_t)NPTS * PITCH];
__device__ __half g_xloB[(size_t)NPTS * PITCH];
__device__ __half g_uA  [(size_t)NPTS * PITCH];
__device__ __half g_uB  [(size_t)NPTS * PITCH];
__device__ float  g_gate[(size_t)11 * NPTS * PITCH];
__device__ __half g_Whi [5600000];
__device__ __half g_Wlo [5600000];
__device__ __half g_Wthi[5600000];
__device__ __half g_Wtlo[5600000];

static const int    LCIN [11] = {259,515,512,512,576,576,768,768,768,960,960};
static const int    LCOUT[11] = {515,512,512,576,576,768,768,768,960,960,896};
static const int    LPIT [11] = {264,520,512,512,576,576,768,768,768,960,960};
static const size_t LWOFF[11] = {0,135960,402200,664344,959256,1291032,1733400,
                                 2323224,2913048,3650328,4571928};
static const int    WTPIT[11] = {520,512,512,576,576,768,768,768,960,960,896};
static const size_t WTOFF[11] = {0,134680,398360,660504,955416,1287192,1729560,
                                 2319384,2909208,3646488,4568088};

__device__ const int    d_LCIN [11] = {259,515,512,512,576,576,768,768,768,960,960};
__device__ const int    d_LCOUT[11] = {515,512,512,576,576,768,768,768,960,960,896};
__device__ const int    d_LPIT [11] = {264,520,512,512,576,576,768,768,768,960,960};
__device__ const size_t d_LWOFF[11] = {0,135960,402200,664344,959256,1291032,1733400,
                                       2323224,2913048,3650328,4571928};
__device__ const int    d_WTPIT[11] = {520,512,512,576,576,768,768,768,960,960,896};
__device__ const size_t d_WTOFF[11] = {0,134680,398360,660504,955416,1287192,1729560,
                                       2319384,2909208,3646488,4568088};

// ---- PTX helpers ----------------------------------------------------------
__device__ __forceinline__ uint32_t smem_u32(const void* p) {
    uint32_t a;
    asm("{ .reg .u64 t; cvta.to.shared.u64 t, %1; cvt.u32.u64 %0, t; }"
        : "=r"(a) : "l"(p));
    return a;
}
__device__ __forceinline__ void cpa16(uint32_t dst, const void* src, int sz) {
    asm volatile("cp.async.cg.shared.global [%0], [%1], 16, %2;"
                 :: "r"(dst), "l"(src), "r"(sz));
}
__device__ __forceinline__ void cpa_commit() {
    asm volatile("cp.async.commit_group;" ::: "memory");
}
__device__ __forceinline__ void ldsm4(uint32_t* r, uint32_t a) {
    asm volatile("ldmatrix.sync.aligned.m8n8.x4.shared.b16 {%0,%1,%2,%3}, [%4];"
                 : "=r"(r[0]), "=r"(r[1]), "=r"(r[2]), "=r"(r[3]) : "r"(a));
}
__device__ __forceinline__ void mma_f16(float* d, const uint32_t* a,
                                        uint32_t b0, uint32_t b1) {
    asm volatile("mma.sync.aligned.m16n8k16.row.col.f32.f16.f16.f32 "
                 "{%0,%1,%2,%3}, {%4,%5,%6,%7}, {%8,%9}, {%0,%1,%2,%3};"
                 : "+f"(d[0]), "+f"(d[1]), "+f"(d[2]), "+f"(d[3])
                 : "r"(a[0]), "r"(a[1]), "r"(a[2]), "r"(a[3]),
                   "r"(b0), "r"(b1));
}
__device__ __forceinline__ void split2h(float v, __half& h, __half& l) {
    h = __float2half_rn(v);
    l = __float2half_rn(v - __half2float(h));
}

// ---- fused W prep: forward + transposed -----------------------------------
struct WPtrs { const float* w[11]; };

__global__ void prep_all_kernel(WPtrs wp)
{
    int l = blockIdx.y;
    int idx = blockIdx.x * blockDim.x + threadIdx.x;
    int cin = d_LCIN[l];
    int cnt = cin * d_LCOUT[l];
    if (idx >= cnt) return;
    int row = idx / cin, col = idx - row * cin;
    __half h, lo;
    split2h(wp.w[l][idx], h, lo);
    size_t d = d_LWOFF[l] + (size_t)row * d_LPIT[l] + col;
    g_Whi[d] = h;
    g_Wlo[d] = lo;
    size_t dt = d_WTOFF[l] + (size_t)col * d_WTPIT[l] + row;
    g_Wthi[dt] = h;
    g_Wtlo[dt] = lo;
}

// ---- init ------------------------------------------------------------------
__global__ void init_kernel(const float* __restrict__ inp,
                            const float* __restrict__ lat,
                            float* __restrict__ out_con)
{
    int idx = blockIdx.x * blockDim.x + threadIdx.x;   // NPTS*259
    if (idx >= NPTS * 259) return;
    int p = idx / 259;
    int c = idx - p * 259;
    int b = p >> 13;
    float v = (c < 3) ? inp[p * 3 + c] : lat[b * 256 + (c - 3)];
    out_con[idx] = v;
    __half h, l;
    split2h(v, h, l);
    size_t xo = (size_t)p * PITCH + c;
    g_xhiA[xo] = h;
    g_xloA[xo] = l;
}

// ---- tile constants: CTA 64(M points) x 128(N), Kc=32, 3 stages -----------
#define STAGES 3
// x stage: Ahi 4K | Alo 4K | Bhi 8K | Blo 8K = 24KB
#define AHI 0
#define ALO 4096
#define BHI 8192
#define BLO 16384
#define STG_X 24576
#define SMEM_X (STAGES * STG_X)
// rev stage: u 4K | Bhi 8K | Blo 8K = 20KB
#define RGA  0
#define RBHI 4096
#define RBLO 12288
#define STG_R 20480
#define SMEM_R (STAGES * STG_R)
#define SWZ64(o) ((o) ^ (((o) >> 3) & 0x30))

// ===========================================================================
// x-layer: 3-term split GEMM + softplus epilogue; gate -> g_gate[goff]
// 128 threads; 4 warps each 64(M) x 32(N).
// ===========================================================================
__global__ void __launch_bounds__(128, 3)
x_kernel(const float* __restrict__ bias, int cin, int cout,
         int wpitch, size_t woff, size_t goff, int flip)
{
    extern __shared__ char smem[];
    __shared__ float bias_s[128];
    const uint32_t sb = smem_u32(smem);
    const int t = threadIdx.x;
    const int lane = t & 31, wid = t >> 5;

    const __half* __restrict__ Xhi = flip ? g_xhiB : g_xhiA;
    const __half* __restrict__ Xlo = flip ? g_xloB : g_xloA;
    __half* __restrict__ Yhi = flip ? g_xhiA : g_xhiB;
    __half* __restrict__ Ylo = flip ? g_xloA : g_xloB;
    float* __restrict__ gate_wr = g_gate + goff;
    const __half* __restrict__ Wh = g_Whi + woff;
    const __half* __restrict__ Wl = g_Wlo + woff;

    const int cblk = blockIdx.x * 128;
    const int nblk = blockIdx.y * 64;

    {
        int c = cblk + t;
        bias_s[t] = (c < cout) ? __ldg(bias + c) : 0.f;
    }

    const int ktiles = (cin + 31) >> 5;

    // 1536 granules/stage, 12 per thread: [0,256) Ahi, [256,512) Alo,
    // [512,1024) Bhi, [1024,1536) Blo.
    auto load_stage = [&](int s, int kt) {
        const uint32_t base = sb + (uint32_t)s * STG_X;
        const int k0 = kt << 5;
        #pragma unroll
        for (int i = 0; i < 12; i++) {
            int gi = t + (i << 7);
            if (gi < 512) {                         // A tiles
                int li = gi & 255;
                int r = li >> 2, g = li & 3;
                int kk = k0 + g * 8, rem = cin - kk;
                int sz = rem >= 8 ? 16 : (rem > 0 ? rem * 2 : 0);
                const __half* src = (gi < 256) ? Xhi : Xlo;
                uint32_t off = (gi < 256) ? AHI : ALO;
                cpa16(base + off + SWZ64((uint32_t)(r * 64 + g * 16)),
                      src + (size_t)(nblk + r) * PITCH + kk, sz);
            } else {                                // B tiles
                int li = (gi - 512) & 511;
                int r = li >> 2, g = li & 3;
                int row = cblk + r;
                int kk = k0 + g * 8, rem = cin - kk;
                int sz = (row < cout) ? (rem >= 8 ? 16 : (rem > 0 ? rem * 2 : 0)) : 0;
                const __half* src = (gi < 1024) ? Wh : Wl;
                uint32_t off = (gi < 1024) ? BHI : BLO;
                cpa16(base + off + SWZ64((uint32_t)(r * 64 + g * 16)),
                      src + (size_t)row * wpitch + kk, sz);
            }
        }
        cpa_commit();
    };

    // fragments: warp covers all 64 M rows, N cols wn*32..wn*32+31
    const int wn = wid;
    const int seg = lane >> 3, i7 = lane & 7;
    uint32_t aR[4], aX[4];
    #pragma unroll
    for (int mi = 0; mi < 4; mi++) {
        int r = mi * 16 + (seg & 1) * 8 + i7;
        aR[mi] = (uint32_t)(r * 64);
        aX[mi] = (aR[mi] >> 3) & 0x30;
    }
    const uint32_t akd = (uint32_t)((seg >> 1) * 16);
    uint32_t bR[2], bX[2];
    #pragma unroll
    for (int np = 0; np < 2; np++) {
        int r = wn * 32 + np * 16 + (seg >> 1) * 8 + i7;
        bR[np] = (uint32_t)(r * 64);
        bX[np] = (bR[np] >> 3) & 0x30;
    }
    const uint32_t bkd = (uint32_t)((seg & 1) * 16);

    float acc[4][4][4];
    #pragma unroll
    for (int mi = 0; mi < 4; mi++)
        #pragma unroll
        for (int ni = 0; ni < 4; ni++)
            #pragma unroll
            for (int r = 0; r < 4; r++) acc[mi][ni][r] = 0.f;

    auto compute = [&](int s) {
        const uint32_t base = sb + (uint32_t)s * STG_X;
        #pragma unroll
        for (int st = 0; st < 2; st++) {
            const uint32_t kb = (uint32_t)(st * 32);
            uint32_t Ah[4][4], Bh[2][4];
            #pragma unroll
            for (int mi = 0; mi < 4; mi++)
                ldsm4(Ah[mi], base + AHI + aR[mi] + ((kb + akd) ^ aX[mi]));
            #pragma unroll
            for (int np = 0; np < 2; np++)
                ldsm4(Bh[np], base + BHI + bR[np] + ((kb + bkd) ^ bX[np]));
            #pragma unroll
            for (int mi = 0; mi < 4; mi++)
                #pragma unroll
                for (int ni = 0; ni < 4; ni++)
                    mma_f16(acc[mi][ni], Ah[mi],
                            Bh[ni >> 1][(ni & 1) * 2], Bh[ni >> 1][(ni & 1) * 2 + 1]);
            {
                uint32_t Al[4][4];
                #pragma unroll
                for (int mi = 0; mi < 4; mi++)
                    ldsm4(Al[mi], base + ALO + aR[mi] + ((kb + akd) ^ aX[mi]));
                #pragma unroll
                for (int mi = 0; mi < 4; mi++)
                    #pragma unroll
                    for (int ni = 0; ni < 4; ni++)
                        mma_f16(acc[mi][ni], Al[mi],
                                Bh[ni >> 1][(ni & 1) * 2], Bh[ni >> 1][(ni & 1) * 2 + 1]);
            }
            {
                uint32_t Bl[2][4];
                #pragma unroll
                for (int np = 0; np < 2; np++)
                    ldsm4(Bl[np], base + BLO + bR[np] + ((kb + bkd) ^ bX[np]));
                #pragma unroll
                for (int mi = 0; mi < 4; mi++)
                    #pragma unroll
                    for (int ni = 0; ni < 4; ni++)
                        mma_f16(acc[mi][ni], Ah[mi],
                                Bl[ni >> 1][(ni & 1) * 2], Bl[ni >> 1][(ni & 1) * 2 + 1]);
            }
        }
    };

    load_stage(0, 0);
    if (ktiles > 1) load_stage(1, 1); else cpa_commit();
    for (int kt = 0; kt < ktiles; kt++) {
        asm volatile("cp.async.wait_group 1;" ::: "memory");
        __syncthreads();
        int nf = kt + 2;
        if (nf < ktiles) load_stage(nf % STAGES, nf); else cpa_commit();
        compute(kt % STAGES);
    }

    const int q = lane >> 2, c2 = (lane & 3) * 2;
    #pragma unroll
    for (int mi = 0; mi < 4; mi++) {
        int r0 = nblk + mi * 16 + q;
        #pragma unroll
        for (int ni = 0; ni < 4; ni++) {
            int nloc = wn * 32 + ni * 8 + c2;
            int cg = cblk + nloc;
            float bv0 = bias_s[nloc], bv1 = bias_s[nloc + 1];
            const float* d = acc[mi][ni];
            #pragma unroll
            for (int rr = 0; rr < 2; rr++) {
                int r = r0 + rr * 8;
                float A0 = 100.f * (d[rr * 2] + bv0);
                float A1 = 100.f * (d[rr * 2 + 1] + bv1);
                float e0 = __expf(-fabsf(A0)), e1 = __expf(-fabsf(A1));
                float sp0 = (fmaxf(A0, 0.f) + __logf(1.f + e0)) * 0.01f;
                float sp1 = (fmaxf(A1, 0.f) + __logf(1.f + e1)) * 0.01f;
                float i0 = __fdividef(1.f, 1.f + e0);
                float i1 = __fdividef(1.f, 1.f + e1);
                float sg0 = (A0 >= 0.f) ? i0 : e0 * i0;
                float sg1 = (A1 >= 0.f) ? i1 : e1 * i1;
                __half h0, l0, h1, l1;
                split2h(sp0, h0, l0);
                split2h(sp1, h1, l1);
                __half* yh = Yhi + (size_t)r * PITCH;
                __half* yl = Ylo + (size_t)r * PITCH;
                float* gp = gate_wr + (size_t)r * PITCH;
                if (cg + 1 < cout) {
                    *(uint32_t*)(yh + cg) = (uint32_t)__half_as_ushort(h0)
                                          | ((uint32_t)__half_as_ushort(h1) << 16);
                    *(uint32_t*)(yl + cg) = (uint32_t)__half_as_ushort(l0)
                                          | ((uint32_t)__half_as_ushort(l1) << 16);
                    *(float2*)(gp + cg) = make_float2(sg0, sg1);
                } else if (cg < cout) {
                    yh[cg] = h0;
                    yl[cg] = l0;
                    gp[cg] = sg0;
                }
            }
        }
    }
}

// ===========================================================================
// reverse step (2-term): r = u · (Wthi + Wtlo), u' = r ⊙ gate[j-1].
// 128 threads; 4 warps each 64(M) x 32(N). u single fp16.
// ===========================================================================
__global__ void __launch_bounds__(128, 3)
rev_kernel(int kdim, int ndim, int wtpit, size_t wtoff, size_t goff, int rp)
{
    extern __shared__ char smem[];
    const uint32_t sb = smem_u32(smem);
    const int t = threadIdx.x;
    const int lane = t & 31, wid = t >> 5;

    const __half* __restrict__ U = rp ? g_uB : g_uA;
    __half* __restrict__ Y = rp ? g_uA : g_uB;
    const float* __restrict__ gate_rd = g_gate + goff;
    const __half* __restrict__ Wh = g_Wthi + wtoff;
    const __half* __restrict__ Wl = g_Wtlo + wtoff;

    const int cblk = blockIdx.x * 128;   // over ndim (cin)
    const int nblk = blockIdx.y * 64;    // over points

    const int ktiles = kdim >> 5;

    // 1280 granules/stage, 10 per thread: [0,256) u, [256,768) Bhi, rest Blo
    auto load_stage = [&](int s, int kt) {
        const uint32_t base = sb + (uint32_t)s * STG_R;
        const int k0 = kt << 5;
        #pragma unroll
        for (int i = 0; i < 10; i++) {
            int gi = t + (i << 7);
            if (gi < 256) {
                int r = gi >> 2, g = gi & 3;
                int kk = k0 + g * 8;
                cpa16(base + RGA + SWZ64((uint32_t)(r * 64 + g * 16)),
                      U + (size_t)(nblk + r) * PITCH + kk, 16);
            } else {
                int li = (gi - 256) & 511;
                int r = li >> 2, g = li & 3;
                int row = cblk + r;
                int kk = k0 + g * 8;
                int sz = (row < ndim) ? 16 : 0;
                const __half* src = (gi < 768) ? Wh : Wl;
                uint32_t off = (gi < 768) ? RBHI : RBLO;
                cpa16(base + off + SWZ64((uint32_t)(r * 64 + g * 16)),
                      src + (size_t)row * wtpit + kk, sz);
            }
        }
        cpa_commit();
    };

    const int wn = wid;
    const int seg = lane >> 3, i7 = lane & 7;
    uint32_t aR[4], aX[4];
    #pragma unroll
    for (int mi = 0; mi < 4; mi++) {
        int r = mi * 16 + (seg & 1) * 8 + i7;
        aR[mi] = (uint32_t)(r * 64);
        aX[mi] = (aR[mi] >> 3) & 0x30;
    }
    const uint32_t akd = (uint32_t)((seg >> 1) * 16);
    uint32_t bR[2], bX[2];
    #pragma unroll
    for (int np = 0; np < 2; np++) {
        int r = wn * 32 + np * 16 + (seg >> 1) * 8 + i7;
        bR[np] = (uint32_t)(r * 64);
        bX[np] = (bR[np] >> 3) & 0x30;
    }
    const uint32_t bkd = (uint32_t)((seg & 1) * 16);

    float acc[4][4][4];
    #pragma unroll
    for (int mi = 0; mi < 4; mi++)
        #pragma unroll
        for (int ni = 0; ni < 4; ni++)
            #pragma unroll
            for (int r = 0; r < 4; r++) acc[mi][ni][r] = 0.f;

    auto compute = [&](int s) {
        const uint32_t base = sb + (uint32_t)s * STG_R;
        #pragma unroll
        for (int st = 0; st < 2; st++) {
            const uint32_t kb = (uint32_t)(st * 32);
            uint32_t Ah[4][4], Bh[2][4];
            #pragma unroll
            for (int mi = 0; mi < 4; mi++)
                ldsm4(Ah[mi], base + RGA + aR[mi] + ((kb + akd) ^ aX[mi]));
            #pragma unroll
            for (int np = 0; np < 2; np++)
                ldsm4(Bh[np], base + RBHI + bR[np] + ((kb + bkd) ^ bX[np]));
            #pragma unroll
            for (int mi = 0; mi < 4; mi++)
                #pragma unroll
                for (int ni = 0; ni < 4; ni++)
                    mma_f16(acc[mi][ni], Ah[mi],
                            Bh[ni >> 1][(ni & 1) * 2], Bh[ni >> 1][(ni & 1) * 2 + 1]);
            {
                uint32_t Bl[2][4];
                #pragma unroll
                for (int np = 0; np < 2; np++)
                    ldsm4(Bl[np], base + RBLO + bR[np] + ((kb + bkd) ^ bX[np]));
                #pragma unroll
                for (int mi = 0; mi < 4; mi++)
                    #pragma unroll
                    for (int ni = 0; ni < 4; ni++)
                        mma_f16(acc[mi][ni], Ah[mi],
                                Bl[ni >> 1][(ni & 1) * 2], Bl[ni >> 1][(ni & 1) * 2 + 1]);
            }
        }
    };

    load_stage(0, 0);
    if (ktiles > 1) load_stage(1, 1); else cpa_commit();
    for (int kt = 0; kt < ktiles; kt++) {
        asm volatile("cp.async.wait_group 1;" ::: "memory");
        __syncthreads();
        int nf = kt + 2;
        if (nf < ktiles) load_stage(nf % STAGES, nf); else cpa_commit();
        compute(kt % STAGES);
    }

    const int q = lane >> 2, c2 = (lane & 3) * 2;
    #pragma unroll
    for (int mi = 0; mi < 4; mi++) {
        int r0 = nblk + mi * 16 + q;
        #pragma unroll
        for (int rr = 0; rr < 2; rr++) {
            int r = r0 + rr * 8;
            const float* gp = gate_rd + (size_t)r * PITCH;
            __half* yr = Y + (size_t)r * PITCH;
            #pragma unroll
            for (int ni = 0; ni < 4; ni++) {
                int cg = cblk + wn * 32 + ni * 8 + c2;
                float d0 = acc[mi][ni][rr * 2], d1 = acc[mi][ni][rr * 2 + 1];
                if (cg + 1 < ndim) {
                    float2 sg = *(const float2*)(gp + cg);
                    __half h0 = __float2half_rn(sg.x * d0);
                    __half h1 = __float2half_rn(sg.y * d1);
                    *(uint32_t*)(yr + cg) = (uint32_t)__half_as_ushort(h0)
                                          | ((uint32_t)__half_as_ushort(h1) << 16);
                } else if (cg < ndim) {
                    yr[cg] = __float2half_rn(gp[cg] * d0);
                }
            }
        }
    }
}

// ---- seed: u11 = W12 ⊙ gate[10] -------------------------------------------
__global__ void seed_kernel(const float* __restrict__ W12)
{
    int idx = blockIdx.x * blockDim.x + threadIdx.x;   // NPTS*896
    if (idx >= NPTS * 896) return;
    int p = idx / 896;
    int o = idx - p * 896;
    float v = __ldg(W12 + o) * g_gate[(size_t)10 * NPTS * PITCH
                                      + (size_t)p * PITCH + o];
    g_uA[(size_t)p * PITCH + o] = __float2half_rn(v);
}

// ---- final: z = W12·x11 + b; g = u1 · W1[:, 0:3] --------------------------
__global__ void final_kernel(const float* __restrict__ W12,
                             const float* __restrict__ b12,
                             const float* __restrict__ W1,
                             float* __restrict__ out)
{
    int gw = (blockIdx.x * blockDim.x + threadIdx.x) >> 5;
    int lane = threadIdx.x & 31;
    if (gw >= 2 * NPTS) return;
    if (gw < NPTS) {                         // z row
        const __half* hp = g_xhiB + (size_t)gw * PITCH;
        const __half* lp = g_xloB + (size_t)gw * PITCH;
        float s = 0.f;
        for (int i = lane; i < 112; i += 32) {
            uint4 hv = *(const uint4*)(hp + i * 8);
            uint4 lv = *(const uint4*)(lp + i * 8);
            float4 w0 = __ldg((const float4*)W12 + i * 2);
            float4 w1 = __ldg((const float4*)W12 + i * 2 + 1);
            const uint32_t* hw = &hv.x;
            const uint32_t* lw = &lv.x;
            float wf2[8] = {w0.x, w0.y, w0.z, w0.w, w1.x, w1.y, w1.z, w1.w};
            #pragma unroll
            for (int qq = 0; qq < 4; qq++) {
                float2 fh = __half22float2(*(const __half2*)&hw[qq]);
                float2 fl = __half22float2(*(const __half2*)&lw[qq]);
                s = fmaf(wf2[2 * qq],     fh.x + fl.x, s);
                s = fmaf(wf2[2 * qq + 1], fh.y + fl.y, s);
            }
        }
        #pragma unroll
        for (int o = 16; o; o >>= 1) s += __shfl_xor_sync(0xffffffffu, s, o);
        if (lane == 0) out[gw] = s + b12[0];
    } else {                                 // gradient: u1 · W1[:,0:3]
        int p = gw - NPTS;
        const __half* hp = g_uA + (size_t)p * PITCH;   // j=1 writes A
        float s0 = 0.f, s1 = 0.f, s2 = 0.f;
        for (int o = lane; o < 515; o += 32) {
            float u = __half2float(hp[o]);
            const float* wr = W1 + (size_t)o * 259;
            s0 = fmaf(u, __ldg(wr),     s0);
            s1 = fmaf(u, __ldg(wr + 1), s1);
            s2 = fmaf(u, __ldg(wr + 2), s2);
        }
        #pragma unroll
        for (int o = 16; o; o >>= 1) {
            s0 += __shfl_xor_sync(0xffffffffu, s0, o);
            s1 += __shfl_xor_sync(0xffffffffu, s1, o);
            s2 += __shfl_xor_sync(0xffffffffu, s2, o);
        }
        if (lane == 0) {
            float* go = out + NPTS + 3 * (size_t)p;
            go[0] = s0; go[1] = s1; go[2] = s2;
        }
    }
}

// ---------------------------------------------------------------------------
extern "C" void kernel_launch(void* const* d_in, const int* in_sizes, int n_in,
                              void* d_out, int out_size)
{
    const float* input  = (const float*)d_in[0];
    const float* latent = (const float*)d_in[1];
    float* out = (float*)d_out;
    float* out_con = out + NPTS + NPTS * 3;

    {
        WPtrs wp;
        for (int l = 0; l < 11; l++) wp.w[l] = (const float*)d_in[2 + 2 * l];
        dim3 grid((960 * 960 + 255) / 256, 11);
        prep_all_kernel<<<grid, 256>>>(wp);
    }
    {
        int tot = NPTS * 259;
        init_kernel<<<(tot + 255) / 256, 256>>>(input, latent, out_con);
    }

    cudaFuncSetAttribute(x_kernel,
                         cudaFuncAttributeMaxDynamicSharedMemorySize, SMEM_X);
    cudaFuncSetAttribute(rev_kernel,
                         cudaFuncAttributeMaxDynamicSharedMemorySize, SMEM_R);

    // forward x-pass, storing all gates
    for (int l = 0; l < 11; l++) {
        const float* b = (const float*)d_in[3 + 2 * l];
        dim3 grid((LCOUT[l] + 127) / 128, NPTS / 64);
        x_kernel<<<grid, 128, SMEM_X>>>(b, LCIN[l], LCOUT[l],
                                        LPIT[l], LWOFF[l],
                                        (size_t)l * NPTS * PITCH, l & 1);
    }

    // reverse sweep: seed u11, then j = 10 .. 1
    seed_kernel<<<(NPTS * 896 + 255) / 256, 256>>>((const float*)d_in[24]);
    for (int j = 10; j >= 1; j--) {
        int kdim = LCOUT[j];
        int ndim = LCIN[j];
        dim3 grid((ndim + 127) / 128, NPTS / 64);
        rev_kernel<<<grid, 128, SMEM_R>>>(kdim, ndim, WTPIT[j], WTOFF[j],
                                          (size_t)(j - 1) * NPTS * PITCH,
                                          (10 - j) & 1);
    }

    final_kernel<<<2 * NPTS * 32 / 256, 256>>>((const float*)d_in[24],
                                               (const float*)d_in[25],
                                               (const float*)d_in[2], out);
}